// round 9
// baseline (speedup 1.0000x reference)
#include <cuda_runtime.h>
#include <cuda_fp16.h>
#include <math.h>

#define NN 50000
#define EE 800000
#define ET 850000   // EE + NN self loops
#define IN_DIM 128
#define HID 128
#define HEADS 8
#define OUT_DIM 64
#define NEG_SLOPE 0.2f
#define SCAN_T 1024
#define SCAN_CHUNK 49   // 1024*49 = 50176 >= NN

// ---------------- scratch (device globals; no allocation) ----------------
__device__ __align__(16) __half g_h1h[NN * HID];     // fp16 layer1 features
__device__ __align__(16) float g_a1s[NN * HEADS];
__device__ __align__(16) float g_a1d[NN * HEADS];
__device__ __align__(16) float g_out1[NN * HID];     // normalized layer1 agg (fp32)
__device__ __align__(16) __half g_h2h[NN * OUT_DIM]; // fp16 layer2 features
__device__ __align__(16) float g_a2s[NN];
__device__ __align__(16) float g_a2d[NN];
__device__ __align__(8)  int2  g_edge[ET];           // (src, dst)
__device__ int g_deg[NN];
__device__ int g_ptr[NN + 1];
__device__ int g_pos[NN];
__device__ int g_srcs[ET];                           // src sorted by dst
__device__ int g_is64;

__device__ __forceinline__ float leaky(float e) {
    return e > 0.f ? e : NEG_SLOPE * e;
}
// packed f32x2 FMA (FFMA2) — ptxas won't emit this on its own
__device__ __forceinline__ unsigned long long ffma2(unsigned long long a,
                                                    unsigned long long b,
                                                    unsigned long long c) {
    unsigned long long d;
    asm("fma.rn.f32x2 %0, %1, %2, %3;" : "=l"(d) : "l"(a), "l"(b), "l"(c));
    return d;
}
__device__ __forceinline__ unsigned long long pack2(float lo, float hi) {
    unsigned long long r;
    asm("mov.b64 %0, {%1, %2};" : "=l"(r) : "f"(lo), "f"(hi));
    return r;
}
__device__ __forceinline__ void unpack2(unsigned long long v, float& lo, float& hi) {
    asm("mov.b64 {%0, %1}, %2;" : "=f"(lo), "=f"(hi) : "l"(v));
}

// ---------------- K0a: detect edge_index dtype (int64 vs int32) ---------------
__global__ void k0_detect(const long long* __restrict__ ei) {
    __shared__ int bad;
    if (threadIdx.x == 0) bad = 0;
    __syncthreads();
    for (int i = threadIdx.x; i < 256; i += blockDim.x) {
        long long v = ei[i];
        if (v < 0 || v >= (long long)NN) bad = 1;
    }
    __syncthreads();
    if (threadIdx.x == 0) g_is64 = bad ? 0 : 1;
}

// ---------------- K0b: decode edges (+self loops) + degree histogram ----------
__global__ void k0_decode(const void* __restrict__ eiv) {
    const int i = blockIdx.x * blockDim.x + threadIdx.x;
    if (i >= ET) return;
    int s, d;
    if (i >= EE) {
        s = d = i - EE;
    } else if (g_is64) {
        const long long* e = (const long long*)eiv;
        s = (int)e[i]; d = (int)e[EE + i];
    } else {
        const int* e = (const int*)eiv;
        s = e[i]; d = e[EE + i];
    }
    g_edge[i] = make_int2(s, d);
    atomicAdd(&g_deg[d], 1);
}

// ---------------- K0c: exclusive scan of degrees (single block) ---------------
__global__ void k0_scan() {
    __shared__ int partial[SCAN_T];
    const int t = threadIdx.x;
    const int start = t * SCAN_CHUNK;
    const int end = min(start + SCAN_CHUNK, NN);
    int sum = 0;
    for (int i = start; i < end; i++) sum += g_deg[i];
    partial[t] = sum;
    __syncthreads();
    for (int dd = 1; dd < SCAN_T; dd <<= 1) {
        int v = (t >= dd) ? partial[t - dd] : 0;
        __syncthreads();
        partial[t] += v;
        __syncthreads();
    }
    int off = partial[t] - sum;  // exclusive prefix
    for (int i = start; i < end; i++) {
        g_ptr[i] = off;
        g_pos[i] = off;
        off += g_deg[i];
    }
    if (t == SCAN_T - 1) g_ptr[NN] = partial[SCAN_T - 1];
}

// ---------------- K0d: scatter srcs into dst-sorted order (4 edges/thread) ----
__global__ void k0_scatter() {
    const int i0 = (blockIdx.x * blockDim.x + threadIdx.x) * 4;
#pragma unroll
    for (int k = 0; k < 4; k++) {
        const int i = i0 + k;
        if (i < ET) {
            const int2 sd = g_edge[i];
            const int p = atomicAdd(&g_pos[sd.y], 1);
            g_srcs[p] = sd.x;
        }
    }
}

// ---------------- K1: h1 = x @ W1 (FFMA2) + per-head attention dots ----------
// 128 threads (= out channel), 8 nodes per block; xst transposed for f32x2.
__global__ void k1_gemm1(const float* __restrict__ x, const float* __restrict__ W1,
                         const float* __restrict__ as1, const float* __restrict__ ad1) {
    __shared__ __align__(16) float xst[IN_DIM][8];   // [k][node]
    const int t = threadIdx.x;
    const int n0 = blockIdx.x * 8;

    for (int i = t; i < 8 * IN_DIM; i += 128) {
        const int j = i >> 7, k = i & 127;
        xst[k][j] = x[n0 * IN_DIM + i];
    }
    __syncthreads();

    unsigned long long acc2[4] = {0ull, 0ull, 0ull, 0ull};
#pragma unroll
    for (int k = 0; k < IN_DIM; k++) {
        const float w = W1[k * HID + t];
        const unsigned long long w2 = pack2(w, w);
#pragma unroll
        for (int jj = 0; jj < 4; jj++) {
            const unsigned long long xv =
                *(const unsigned long long*)&xst[k][jj * 2];
            acc2[jj] = ffma2(xv, w2, acc2[jj]);
        }
    }

    float accf[8];
#pragma unroll
    for (int jj = 0; jj < 4; jj++) unpack2(acc2[jj], accf[jj * 2], accf[jj * 2 + 1]);

    const float vas = as1[t], vad = ad1[t];
#pragma unroll
    for (int j = 0; j < 8; j++) {
        g_h1h[(n0 + j) * HID + t] = __float2half(accf[j]);
        float vs = accf[j] * vas, vd = accf[j] * vad;
#pragma unroll
        for (int o = 8; o; o >>= 1) {
            vs += __shfl_xor_sync(0xffffffffu, vs, o);
            vd += __shfl_xor_sync(0xffffffffu, vd, o);
        }
        if ((t & 15) == 0) {
            g_a1s[(n0 + j) * HEADS + (t >> 4)] = vs;
            g_a1d[(n0 + j) * HEADS + (t >> 4)] = vd;
        }
    }
}

// ---------------- K3: CSR layer1 aggregation (warp per dst node) --------------
// lane owns channels lane*4..+3 of head hq=lane>>2; exp computed redundantly
// in every lane for its own head -> no exp shuffles, no den reduction.
__global__ void k3_agg1() {
    const int d = (blockIdx.x * blockDim.x + threadIdx.x) >> 5;
    const int lane = threadIdx.x & 31;
    if (d >= NN) return;

    const int hq = lane >> 2;
    const float a1d_h = __ldg(&g_a1d[d * HEADS + hq]);

    const int p0 = g_ptr[d], p1 = g_ptr[d + 1];
    float4 acc = make_float4(0.f, 0.f, 0.f, 0.f);
    float den = 0.f;   // per-lane full denominator for head hq

    for (int base = p0; base < p1; base += 32) {
        const int cnt = min(32, p1 - base);
        int s_r = 0;
        if (lane < cnt) s_r = __ldg(&g_srcs[base + lane]);
        for (int j0 = 0; j0 < cnt; j0 += 4) {
#pragma unroll
            for (int e = 0; e < 4; e++) {
                const int j = j0 + e;
                const int jj = min(j, cnt - 1);
                const int s = __shfl_sync(0xffffffffu, s_r, jj);
                const float valid = (j < cnt) ? 1.f : 0.f;
                const float ex =
                    __expf(leaky(__ldg(&g_a1s[s * HEADS + hq]) + a1d_h)) * valid;
                den += ex;
                const __half2* hp = (const __half2*)&g_h1h[s * HID + (lane << 2)];
                const float2 f0 = __half22float2(hp[0]);
                const float2 f1 = __half22float2(hp[1]);
                acc.x += f0.x * ex;
                acc.y += f0.y * ex;
                acc.z += f1.x * ex;
                acc.w += f1.y * ex;
            }
        }
    }
    const float inv = 1.f / (den + 1e-16f);
    acc.x *= inv; acc.y *= inv; acc.z *= inv; acc.w *= inv;
    *(float4*)&g_out1[d * HID + (lane << 2)] = acc;
}

// ---------------- K4: h2 = elu(out1+b1) @ W2 (FFMA2) + attention dots --------
// 64 threads (= out channel), 8 nodes per block.
__global__ void k4_gemm2(const float* __restrict__ W2, const float* __restrict__ b1,
                         const float* __restrict__ as2, const float* __restrict__ ad2) {
    __shared__ __align__(16) float hst[HID][8];      // [k][node]
    __shared__ float rbs[2][8], rbd[2][8];
    const int t = threadIdx.x;
    const int n0 = blockIdx.x * 8;

    for (int i = t; i < 8 * HID; i += 64) {
        const int j = i >> 7, k = i & 127;
        float v = g_out1[n0 * HID + i] + b1[k];
        hst[k][j] = v > 0.f ? v : (__expf(v) - 1.f);
    }
    __syncthreads();

    unsigned long long acc2[4] = {0ull, 0ull, 0ull, 0ull};
#pragma unroll
    for (int k = 0; k < HID; k++) {
        const float w = W2[k * OUT_DIM + t];
        const unsigned long long w2 = pack2(w, w);
#pragma unroll
        for (int jj = 0; jj < 4; jj++) {
            const unsigned long long xv =
                *(const unsigned long long*)&hst[k][jj * 2];
            acc2[jj] = ffma2(xv, w2, acc2[jj]);
        }
    }

    float accf[8];
#pragma unroll
    for (int jj = 0; jj < 4; jj++) unpack2(acc2[jj], accf[jj * 2], accf[jj * 2 + 1]);

    const float vas = as2[t], vad = ad2[t];
    const int wid = t >> 5;
#pragma unroll
    for (int j = 0; j < 8; j++) {
        g_h2h[(n0 + j) * OUT_DIM + t] = __float2half(accf[j]);
        float vs = accf[j] * vas, vd = accf[j] * vad;
#pragma unroll
        for (int o = 16; o; o >>= 1) {
            vs += __shfl_xor_sync(0xffffffffu, vs, o);
            vd += __shfl_xor_sync(0xffffffffu, vd, o);
        }
        if ((t & 31) == 0) { rbs[wid][j] = vs; rbd[wid][j] = vd; }
    }
    __syncthreads();
    if (t < 8) {
        g_a2s[n0 + t] = rbs[0][t] + rbs[1][t];
        g_a2d[n0 + t] = rbd[0][t] + rbd[1][t];
    }
}

// ---------------- K6: CSR layer2 aggregation + bias + log_softmax -------------
// warp per dst node; lane owns 2 channels; redundant exp (broadcast a2s load),
// per-lane full denominator -> no reductions until log_softmax.
__global__ void k6_lsm(const float* __restrict__ b2, float* __restrict__ out) {
    const int d = (blockIdx.x * blockDim.x + threadIdx.x) >> 5;
    const int lane = threadIdx.x & 31;
    if (d >= NN) return;

    const float a2d_d = __ldg(&g_a2d[d]);
    const int p0 = g_ptr[d], p1 = g_ptr[d + 1];
    float2 acc = make_float2(0.f, 0.f);
    float den = 0.f;

    for (int base = p0; base < p1; base += 32) {
        const int cnt = min(32, p1 - base);
        int s_r = 0;
        if (lane < cnt) s_r = __ldg(&g_srcs[base + lane]);
        for (int j0 = 0; j0 < cnt; j0 += 4) {
#pragma unroll
            for (int e = 0; e < 4; e++) {
                const int j = j0 + e;
                const int jj = min(j, cnt - 1);
                const int s = __shfl_sync(0xffffffffu, s_r, jj);
                const float valid = (j < cnt) ? 1.f : 0.f;
                const float ex =
                    __expf(leaky(__ldg(&g_a2s[s]) + a2d_d)) * valid;
                den += ex;
                const float2 f =
                    __half22float2(*(const __half2*)&g_h2h[s * OUT_DIM + lane * 2]);
                acc.x += f.x * ex;
                acc.y += f.y * ex;
            }
        }
    }
    const float inv = 1.f / (den + 1e-16f);

    float vx = acc.x * inv + b2[lane * 2];
    float vy = acc.y * inv + b2[lane * 2 + 1];
    float m = fmaxf(vx, vy);
#pragma unroll
    for (int o = 16; o; o >>= 1) m = fmaxf(m, __shfl_xor_sync(0xffffffffu, m, o));
    float ssum = expf(vx - m) + expf(vy - m);
#pragma unroll
    for (int o = 16; o; o >>= 1) ssum += __shfl_xor_sync(0xffffffffu, ssum, o);
    const float lse = m + logf(ssum);
    *(float2*)&out[d * OUT_DIM + lane * 2] = make_float2(vx - lse, vy - lse);
}

// ---------------- launch ----------------
extern "C" void kernel_launch(void* const* d_in, const int* in_sizes, int n_in,
                              void* d_out, int out_size) {
    const float* x   = (const float*)d_in[0];
    const void*  ei  = d_in[1];
    const float* W1  = (const float*)d_in[2];
    const float* as1 = (const float*)d_in[3];
    const float* ad1 = (const float*)d_in[4];
    const float* b1  = (const float*)d_in[5];
    const float* W2  = (const float*)d_in[6];
    const float* as2 = (const float*)d_in[7];
    const float* ad2 = (const float*)d_in[8];
    const float* b2  = (const float*)d_in[9];
    float* out = (float*)d_out;

    void* pdeg;
    cudaGetSymbolAddress(&pdeg, g_deg);
    cudaMemsetAsync(pdeg, 0, sizeof(int) * NN);

    k0_detect<<<1, 256>>>((const long long*)ei);
    k0_decode<<<(ET + 255) / 256, 256>>>(ei);
    k0_scan<<<1, SCAN_T>>>();
    k0_scatter<<<(ET / 4 + 255) / 256, 256>>>();
    k1_gemm1<<<(NN + 7) / 8, 128>>>(x, W1, as1, ad1);
    k3_agg1<<<(NN + 7) / 8, 256>>>();
    k4_gemm2<<<(NN + 7) / 8, 64>>>(W2, b1, as2, ad2);
    k6_lsm<<<(NN + 7) / 8, 256>>>(b2, out);
}

// round 10
// speedup vs baseline: 1.0395x; 1.0395x over previous
#include <cuda_runtime.h>
#include <cuda_fp16.h>
#include <math.h>

#define NN 50000
#define EE 800000
#define ET 850000   // EE + NN self loops
#define IN_DIM 128
#define HID 128
#define HEADS 8
#define OUT_DIM 64
#define NEG_SLOPE 0.2f
#define SCAN_T 1024
#define SCAN_CHUNK 49   // 1024*49 = 50176 >= NN

// ---------------- scratch (device globals; no allocation) ----------------
__device__ __align__(16) float g_h1[NN * HID];
__device__ __align__(16) float g_a1s[NN * HEADS];
__device__ __align__(16) float g_a1d[NN * HEADS];
__device__ __align__(16) float g_out1[NN * HID];     // normalized layer1 agg
__device__ __align__(16) float g_h2[NN * OUT_DIM];
__device__ __align__(16) float g_a2s[NN];
__device__ __align__(16) float g_a2d[NN];
__device__ int g_deg[NN];
__device__ int g_ptr[NN + 1];
__device__ int g_pos[NN];
__device__ int g_srcs[ET];                           // src sorted by dst
__device__ int g_is64;

__device__ __forceinline__ float leaky(float e) {
    return e > 0.f ? e : NEG_SLOPE * e;
}
// packed f32x2 FMA (FFMA2) — ptxas won't emit this on its own
__device__ __forceinline__ unsigned long long ffma2(unsigned long long a,
                                                    unsigned long long b,
                                                    unsigned long long c) {
    unsigned long long d;
    asm("fma.rn.f32x2 %0, %1, %2, %3;" : "=l"(d) : "l"(a), "l"(b), "l"(c));
    return d;
}
__device__ __forceinline__ unsigned long long pack2(float lo, float hi) {
    unsigned long long r;
    asm("mov.b64 %0, {%1, %2};" : "=l"(r) : "f"(lo), "f"(hi));
    return r;
}
__device__ __forceinline__ void unpack2(unsigned long long v, float& lo, float& hi) {
    asm("mov.b64 {%0, %1}, %2;" : "=f"(lo), "=f"(hi) : "l"(v));
}

// ---------------- K0a: detect edge_index dtype (int64 vs int32) ---------------
__global__ void k0_detect(const long long* __restrict__ ei) {
    __shared__ int bad;
    if (threadIdx.x == 0) bad = 0;
    __syncthreads();
    for (int i = threadIdx.x; i < 256; i += blockDim.x) {
        long long v = ei[i];
        if (v < 0 || v >= (long long)NN) bad = 1;
    }
    __syncthreads();
    if (threadIdx.x == 0) g_is64 = bad ? 0 : 1;
}

// ---------------- K0b: degree histogram (reads dst half directly) -------------
__global__ void k0_hist(const void* __restrict__ eiv) {
    const int i = blockIdx.x * blockDim.x + threadIdx.x;
    if (i >= ET) return;
    int d;
    if (i >= EE) d = i - EE;
    else if (g_is64) d = (int)((const long long*)eiv)[EE + i];
    else d = ((const int*)eiv)[EE + i];
    atomicAdd(&g_deg[d], 1);
}

// ---------------- K0c: exclusive scan of degrees (single block) ---------------
__global__ void k0_scan() {
    __shared__ int partial[SCAN_T];
    const int t = threadIdx.x;
    const int start = t * SCAN_CHUNK;
    const int end = min(start + SCAN_CHUNK, NN);
    int sum = 0;
    for (int i = start; i < end; i++) sum += g_deg[i];
    partial[t] = sum;
    __syncthreads();
    for (int dd = 1; dd < SCAN_T; dd <<= 1) {
        int v = (t >= dd) ? partial[t - dd] : 0;
        __syncthreads();
        partial[t] += v;
        __syncthreads();
    }
    int off = partial[t] - sum;  // exclusive prefix
    for (int i = start; i < end; i++) {
        g_ptr[i] = off;
        g_pos[i] = off;
        off += g_deg[i];
    }
    if (t == SCAN_T - 1) g_ptr[NN] = partial[SCAN_T - 1];
}

// ---------------- K0d: scatter srcs into dst-sorted order ---------------------
__global__ void k0_scatter(const void* __restrict__ eiv) {
    const int i = blockIdx.x * blockDim.x + threadIdx.x;
    if (i >= ET) return;
    int s, d;
    if (i >= EE) {
        s = d = i - EE;
    } else if (g_is64) {
        const long long* e = (const long long*)eiv;
        s = (int)e[i]; d = (int)e[EE + i];
    } else {
        const int* e = (const int*)eiv;
        s = e[i]; d = e[EE + i];
    }
    const int p = atomicAdd(&g_pos[d], 1);
    g_srcs[p] = s;
}

// ---------------- K1: h1 = x @ W1 (FFMA2) + per-head attention dots ----------
// 128 threads (= out channel), 8 nodes per block; xst transposed for f32x2.
__global__ void k1_gemm1(const float* __restrict__ x, const float* __restrict__ W1,
                         const float* __restrict__ as1, const float* __restrict__ ad1) {
    __shared__ __align__(16) float xst[IN_DIM][8];   // [k][node]
    const int t = threadIdx.x;
    const int n0 = blockIdx.x * 8;

    for (int i = t; i < 8 * IN_DIM; i += 128) {
        const int j = i >> 7, k = i & 127;
        xst[k][j] = x[n0 * IN_DIM + i];
    }
    __syncthreads();

    unsigned long long acc2[4] = {0ull, 0ull, 0ull, 0ull};
#pragma unroll
    for (int k = 0; k < IN_DIM; k++) {
        const float w = W1[k * HID + t];
        const unsigned long long w2 = pack2(w, w);
#pragma unroll
        for (int jj = 0; jj < 4; jj++) {
            const unsigned long long xv =
                *(const unsigned long long*)&xst[k][jj * 2];
            acc2[jj] = ffma2(xv, w2, acc2[jj]);
        }
    }

    float accf[8];
#pragma unroll
    for (int jj = 0; jj < 4; jj++) unpack2(acc2[jj], accf[jj * 2], accf[jj * 2 + 1]);

    const float vas = as1[t], vad = ad1[t];
#pragma unroll
    for (int j = 0; j < 8; j++) {
        g_h1[(n0 + j) * HID + t] = accf[j];
        float vs = accf[j] * vas, vd = accf[j] * vad;
#pragma unroll
        for (int o = 8; o; o >>= 1) {
            vs += __shfl_xor_sync(0xffffffffu, vs, o);
            vd += __shfl_xor_sync(0xffffffffu, vd, o);
        }
        if ((t & 15) == 0) {
            g_a1s[(n0 + j) * HEADS + (t >> 4)] = vs;
            g_a1d[(n0 + j) * HEADS + (t >> 4)] = vd;
        }
    }
}

// ---------------- K3: CSR layer1 aggregation (warp per dst node) --------------
// 8-edge batches: explicit load arrays force MLP=8 on the h1 gathers.
// lane = e*8+h computes exps for edges j0+e (round A) / j0+4+e (round B).
__global__ void k3_agg1() {
    const int d = (blockIdx.x * blockDim.x + threadIdx.x) >> 5;
    const int lane = threadIdx.x & 31;
    if (d >= NN) return;

    const int hq = lane >> 2;     // accumulation head (4 lanes each)
    const int esel = lane >> 3;   // 0..3: edge-in-group for exp duty
    const int hsel = lane & 7;    // head for exp duty
    const float a1d_h = (lane < 8) ? __ldg(&g_a1d[d * HEADS + lane]) : 0.f;
    const float a1d_all = __shfl_sync(0xffffffffu, a1d_h, hsel);

    const int p0 = g_ptr[d], p1 = g_ptr[d + 1];
    float4 acc = make_float4(0.f, 0.f, 0.f, 0.f);
    float den_part = 0.f;

    for (int base = p0; base < p1; base += 32) {
        const int cnt = min(32, p1 - base);
        int s_r = 0;
        if (lane < cnt) s_r = __ldg(&g_srcs[base + lane]);
        for (int j0 = 0; j0 < cnt; j0 += 8) {
            const int ja = j0 + esel;
            const int jb = j0 + 4 + esel;
            const int sa = __shfl_sync(0xffffffffu, s_r, min(ja, cnt - 1));
            const int sb = __shfl_sync(0xffffffffu, s_r, min(jb, cnt - 1) & 31);
            const float ex0 = (ja < cnt)
                ? __expf(leaky(__ldg(&g_a1s[sa * HEADS + hsel]) + a1d_all)) : 0.f;
            const float ex1 = (jb < cnt)
                ? __expf(leaky(__ldg(&g_a1s[sb * HEADS + hsel]) + a1d_all)) : 0.f;
            den_part += ex0 + ex1;

            float4 hv[8];
#pragma unroll
            for (int e = 0; e < 8; e++) {
                const int s2 = __shfl_sync(0xffffffffu, s_r, min(j0 + e, cnt - 1));
                hv[e] = *(const float4*)&g_h1[s2 * HID + (lane << 2)];
            }
#pragma unroll
            for (int e = 0; e < 8; e++) {
                const float exs = (e < 4) ? ex0 : ex1;
                const float exh = __shfl_sync(0xffffffffu, exs, ((e & 3) << 3) | hq);
                acc.x += hv[e].x * exh;
                acc.y += hv[e].y * exh;
                acc.z += hv[e].z * exh;
                acc.w += hv[e].w * exh;
            }
        }
    }
    // lanes e*8+h hold den partials for head h: fold over e
    den_part += __shfl_xor_sync(0xffffffffu, den_part, 8);
    den_part += __shfl_xor_sync(0xffffffffu, den_part, 16);
    const float den = __shfl_sync(0xffffffffu, den_part, hq);
    const float inv = 1.f / (den + 1e-16f);
    acc.x *= inv; acc.y *= inv; acc.z *= inv; acc.w *= inv;
    *(float4*)&g_out1[d * HID + (lane << 2)] = acc;
}

// ---------------- K4: h2 = elu(out1+b1) @ W2 (FFMA2) + attention dots --------
// 64 threads (= out channel), 8 nodes per block.
__global__ void k4_gemm2(const float* __restrict__ W2, const float* __restrict__ b1,
                         const float* __restrict__ as2, const float* __restrict__ ad2) {
    __shared__ __align__(16) float hst[HID][8];      // [k][node]
    __shared__ float rbs[2][8], rbd[2][8];
    const int t = threadIdx.x;
    const int n0 = blockIdx.x * 8;

    for (int i = t; i < 8 * HID; i += 64) {
        const int j = i >> 7, k = i & 127;
        float v = g_out1[n0 * HID + i] + b1[k];
        hst[k][j] = v > 0.f ? v : (__expf(v) - 1.f);
    }
    __syncthreads();

    unsigned long long acc2[4] = {0ull, 0ull, 0ull, 0ull};
#pragma unroll
    for (int k = 0; k < HID; k++) {
        const float w = W2[k * OUT_DIM + t];
        const unsigned long long w2 = pack2(w, w);
#pragma unroll
        for (int jj = 0; jj < 4; jj++) {
            const unsigned long long xv =
                *(const unsigned long long*)&hst[k][jj * 2];
            acc2[jj] = ffma2(xv, w2, acc2[jj]);
        }
    }

    float accf[8];
#pragma unroll
    for (int jj = 0; jj < 4; jj++) unpack2(acc2[jj], accf[jj * 2], accf[jj * 2 + 1]);

    const float vas = as2[t], vad = ad2[t];
    const int wid = t >> 5;
#pragma unroll
    for (int j = 0; j < 8; j++) {
        g_h2[(n0 + j) * OUT_DIM + t] = accf[j];
        float vs = accf[j] * vas, vd = accf[j] * vad;
#pragma unroll
        for (int o = 16; o; o >>= 1) {
            vs += __shfl_xor_sync(0xffffffffu, vs, o);
            vd += __shfl_xor_sync(0xffffffffu, vd, o);
        }
        if ((t & 31) == 0) { rbs[wid][j] = vs; rbd[wid][j] = vd; }
    }
    __syncthreads();
    if (t < 8) {
        g_a2s[n0 + t] = rbs[0][t] + rbs[1][t];
        g_a2d[n0 + t] = rbd[0][t] + rbd[1][t];
    }
}

// ---------------- K6: CSR layer2 aggregation + bias + log_softmax -------------
// warp per dst node; lane owns 2 channels; one exp per lane per 32-edge chunk;
// 8-edge batched gathers for MLP.
__global__ void k6_lsm(const float* __restrict__ b2, float* __restrict__ out) {
    const int d = (blockIdx.x * blockDim.x + threadIdx.x) >> 5;
    const int lane = threadIdx.x & 31;
    if (d >= NN) return;

    const float a2d_d = __ldg(&g_a2d[d]);
    const int p0 = g_ptr[d], p1 = g_ptr[d + 1];
    float2 acc = make_float2(0.f, 0.f);
    float den = 0.f;

    for (int base = p0; base < p1; base += 32) {
        const int cnt = min(32, p1 - base);
        int s_r = 0;
        float e_r = 0.f;
        if (lane < cnt) {
            s_r = __ldg(&g_srcs[base + lane]);
            e_r = __expf(leaky(__ldg(&g_a2s[s_r]) + a2d_d));
            den += e_r;
        }
        for (int j0 = 0; j0 < cnt; j0 += 8) {
            float2 hv[8];
            float exv[8];
#pragma unroll
            for (int e = 0; e < 8; e++) {
                const int jj = (j0 + e) & 31;
                const int s = __shfl_sync(0xffffffffu, s_r, jj);
                exv[e] = __shfl_sync(0xffffffffu, e_r, jj);
                hv[e] = *(const float2*)&g_h2[s * OUT_DIM + lane * 2];
            }
#pragma unroll
            for (int e = 0; e < 8; e++) {
                acc.x += hv[e].x * exv[e];
                acc.y += hv[e].y * exv[e];
            }
        }
    }
#pragma unroll
    for (int o = 16; o; o >>= 1) den += __shfl_xor_sync(0xffffffffu, den, o);
    const float inv = 1.f / (den + 1e-16f);

    float vx = acc.x * inv + b2[lane * 2];
    float vy = acc.y * inv + b2[lane * 2 + 1];
    float m = fmaxf(vx, vy);
#pragma unroll
    for (int o = 16; o; o >>= 1) m = fmaxf(m, __shfl_xor_sync(0xffffffffu, m, o));
    float ssum = expf(vx - m) + expf(vy - m);
#pragma unroll
    for (int o = 16; o; o >>= 1) ssum += __shfl_xor_sync(0xffffffffu, ssum, o);
    const float lse = m + logf(ssum);
    *(float2*)&out[d * OUT_DIM + lane * 2] = make_float2(vx - lse, vy - lse);
}

// ---------------- launch ----------------
extern "C" void kernel_launch(void* const* d_in, const int* in_sizes, int n_in,
                              void* d_out, int out_size) {
    const float* x   = (const float*)d_in[0];
    const void*  ei  = d_in[1];
    const float* W1  = (const float*)d_in[2];
    const float* as1 = (const float*)d_in[3];
    const float* ad1 = (const float*)d_in[4];
    const float* b1  = (const float*)d_in[5];
    const float* W2  = (const float*)d_in[6];
    const float* as2 = (const float*)d_in[7];
    const float* ad2 = (const float*)d_in[8];
    const float* b2  = (const float*)d_in[9];
    float* out = (float*)d_out;

    void* pdeg;
    cudaGetSymbolAddress(&pdeg, g_deg);
    cudaMemsetAsync(pdeg, 0, sizeof(int) * NN);

    k0_detect<<<1, 256>>>((const long long*)ei);
    k0_hist<<<(ET + 255) / 256, 256>>>(ei);
    k0_scan<<<1, SCAN_T>>>();
    k0_scatter<<<(ET + 255) / 256, 256>>>(ei);
    k1_gemm1<<<(NN + 7) / 8, 128>>>(x, W1, as1, ad1);
    k3_agg1<<<(NN + 7) / 8, 256>>>();
    k4_gemm2<<<(NN + 7) / 8, 64>>>(W2, b1, as2, ad2);
    k6_lsm<<<(NN + 7) / 8, 256>>>(b2, out);
}

// round 11
// speedup vs baseline: 1.0584x; 1.0182x over previous
#include <cuda_runtime.h>
#include <cuda_fp16.h>
#include <math.h>

#define NN 50000
#define EE 800000
#define ET 850000   // EE + NN self loops
#define IN_DIM 128
#define HID 128
#define HEADS 8
#define OUT_DIM 64
#define NEG_SLOPE 0.2f
#define SCAN_T 1024
#define SCAN_CHUNK 49   // 1024*49 = 50176 >= NN

// ---------------- scratch (device globals; no allocation) ----------------
__device__ __align__(16) float g_h1[NN * HID];
__device__ __align__(16) float g_a1s[NN * HEADS];
__device__ __align__(16) float g_a1d[NN * HEADS];
__device__ __align__(16) float g_out1[NN * HID];     // normalized layer1 agg
__device__ __align__(16) float g_h2[NN * OUT_DIM];
__device__ __align__(16) float g_a2s[NN];
__device__ __align__(16) float g_a2d[NN];
__device__ int g_deg[NN];
__device__ int g_ptr[NN + 1];
__device__ int g_pos[NN];
__device__ int g_srcs[ET];                           // src sorted by dst
__device__ int g_is64;

__device__ __forceinline__ float leaky(float e) {
    return e > 0.f ? e : NEG_SLOPE * e;
}
// packed f32x2 FMA (FFMA2) — ptxas won't emit this on its own
__device__ __forceinline__ unsigned long long ffma2(unsigned long long a,
                                                    unsigned long long b,
                                                    unsigned long long c) {
    unsigned long long d;
    asm("fma.rn.f32x2 %0, %1, %2, %3;" : "=l"(d) : "l"(a), "l"(b), "l"(c));
    return d;
}
__device__ __forceinline__ unsigned long long pack2(float lo, float hi) {
    unsigned long long r;
    asm("mov.b64 %0, {%1, %2};" : "=l"(r) : "f"(lo), "f"(hi));
    return r;
}
__device__ __forceinline__ void unpack2(unsigned long long v, float& lo, float& hi) {
    asm("mov.b64 {%0, %1}, %2;" : "=f"(lo), "=f"(hi) : "l"(v));
}

// ---------------- K0a: detect edge_index dtype (int64 vs int32) ---------------
__global__ void k0_detect(const long long* __restrict__ ei) {
    __shared__ int bad;
    if (threadIdx.x == 0) bad = 0;
    __syncthreads();
    for (int i = threadIdx.x; i < 256; i += blockDim.x) {
        long long v = ei[i];
        if (v < 0 || v >= (long long)NN) bad = 1;
    }
    __syncthreads();
    if (threadIdx.x == 0) g_is64 = bad ? 0 : 1;
}

// ---------------- K0b: degree histogram (reads dst half directly) -------------
__global__ void k0_hist(const void* __restrict__ eiv) {
    const int i = blockIdx.x * blockDim.x + threadIdx.x;
    if (i >= ET) return;
    int d;
    if (i >= EE) d = i - EE;
    else if (g_is64) d = (int)((const long long*)eiv)[EE + i];
    else d = ((const int*)eiv)[EE + i];
    atomicAdd(&g_deg[d], 1);
}

// ---------------- K0c: exclusive scan of degrees (single block) ---------------
__global__ void k0_scan() {
    __shared__ int partial[SCAN_T];
    const int t = threadIdx.x;
    const int start = t * SCAN_CHUNK;
    const int end = min(start + SCAN_CHUNK, NN);
    int sum = 0;
    for (int i = start; i < end; i++) sum += g_deg[i];
    partial[t] = sum;
    __syncthreads();
    for (int dd = 1; dd < SCAN_T; dd <<= 1) {
        int v = (t >= dd) ? partial[t - dd] : 0;
        __syncthreads();
        partial[t] += v;
        __syncthreads();
    }
    int off = partial[t] - sum;  // exclusive prefix
    for (int i = start; i < end; i++) {
        g_ptr[i] = off;
        g_pos[i] = off;
        off += g_deg[i];
    }
    if (t == SCAN_T - 1) g_ptr[NN] = partial[SCAN_T - 1];
}

// ---------------- K0d: scatter srcs into dst-sorted order ---------------------
__global__ void k0_scatter(const void* __restrict__ eiv) {
    const int i = blockIdx.x * blockDim.x + threadIdx.x;
    if (i >= ET) return;
    int s, d;
    if (i >= EE) {
        s = d = i - EE;
    } else if (g_is64) {
        const long long* e = (const long long*)eiv;
        s = (int)e[i]; d = (int)e[EE + i];
    } else {
        const int* e = (const int*)eiv;
        s = e[i]; d = e[EE + i];
    }
    const int p = atomicAdd(&g_pos[d], 1);
    g_srcs[p] = s;
}

// ---------------- K1: h1 = x @ W1 (FFMA2) + per-head attention dots ----------
// 128 threads (= out channel), 8 nodes per block; xst transposed for f32x2.
__global__ void k1_gemm1(const float* __restrict__ x, const float* __restrict__ W1,
                         const float* __restrict__ as1, const float* __restrict__ ad1) {
    __shared__ __align__(16) float xst[IN_DIM][8];   // [k][node]
    const int t = threadIdx.x;
    const int n0 = blockIdx.x * 8;

    for (int i = t; i < 8 * IN_DIM; i += 128) {
        const int j = i >> 7, k = i & 127;
        xst[k][j] = x[n0 * IN_DIM + i];
    }
    __syncthreads();

    unsigned long long acc2[4] = {0ull, 0ull, 0ull, 0ull};
#pragma unroll
    for (int k = 0; k < IN_DIM; k++) {
        const float w = W1[k * HID + t];
        const unsigned long long w2 = pack2(w, w);
#pragma unroll
        for (int jj = 0; jj < 4; jj++) {
            const unsigned long long xv =
                *(const unsigned long long*)&xst[k][jj * 2];
            acc2[jj] = ffma2(xv, w2, acc2[jj]);
        }
    }

    float accf[8];
#pragma unroll
    for (int jj = 0; jj < 4; jj++) unpack2(acc2[jj], accf[jj * 2], accf[jj * 2 + 1]);

    const float vas = as1[t], vad = ad1[t];
#pragma unroll
    for (int j = 0; j < 8; j++) {
        g_h1[(n0 + j) * HID + t] = accf[j];
        float vs = accf[j] * vas, vd = accf[j] * vad;
#pragma unroll
        for (int o = 8; o; o >>= 1) {
            vs += __shfl_xor_sync(0xffffffffu, vs, o);
            vd += __shfl_xor_sync(0xffffffffu, vd, o);
        }
        if ((t & 15) == 0) {
            g_a1s[(n0 + j) * HEADS + (t >> 4)] = vs;
            g_a1d[(n0 + j) * HEADS + (t >> 4)] = vd;
        }
    }
}

// ---------------- K3: CSR layer1 aggregation (warp per dst node) --------------
// 8-edge batches: explicit load arrays force MLP=8 on the h1 gathers.
// lane = e*8+h computes exps for edges j0+e (round A) / j0+4+e (round B).
__global__ void k3_agg1() {
    const int d = (blockIdx.x * blockDim.x + threadIdx.x) >> 5;
    const int lane = threadIdx.x & 31;
    if (d >= NN) return;

    const int hq = lane >> 2;     // accumulation head (4 lanes each)
    const int esel = lane >> 3;   // 0..3: edge-in-group for exp duty
    const int hsel = lane & 7;    // head for exp duty
    const float a1d_h = (lane < 8) ? __ldg(&g_a1d[d * HEADS + lane]) : 0.f;
    const float a1d_all = __shfl_sync(0xffffffffu, a1d_h, hsel);

    const int p0 = g_ptr[d], p1 = g_ptr[d + 1];
    float4 acc = make_float4(0.f, 0.f, 0.f, 0.f);
    float den_part = 0.f;

    for (int base = p0; base < p1; base += 32) {
        const int cnt = min(32, p1 - base);
        int s_r = 0;
        if (lane < cnt) s_r = __ldg(&g_srcs[base + lane]);
        for (int j0 = 0; j0 < cnt; j0 += 8) {
            const int ja = j0 + esel;
            const int jb = j0 + 4 + esel;
            const int sa = __shfl_sync(0xffffffffu, s_r, min(ja, cnt - 1));
            const int sb = __shfl_sync(0xffffffffu, s_r, min(jb, cnt - 1) & 31);
            const float ex0 = (ja < cnt)
                ? __expf(leaky(__ldg(&g_a1s[sa * HEADS + hsel]) + a1d_all)) : 0.f;
            const float ex1 = (jb < cnt)
                ? __expf(leaky(__ldg(&g_a1s[sb * HEADS + hsel]) + a1d_all)) : 0.f;
            den_part += ex0 + ex1;

            float4 hv[8];
#pragma unroll
            for (int e = 0; e < 8; e++) {
                const int s2 = __shfl_sync(0xffffffffu, s_r, min(j0 + e, cnt - 1));
                hv[e] = *(const float4*)&g_h1[s2 * HID + (lane << 2)];
            }
#pragma unroll
            for (int e = 0; e < 8; e++) {
                const float exs = (e < 4) ? ex0 : ex1;
                const float exh = __shfl_sync(0xffffffffu, exs, ((e & 3) << 3) | hq);
                acc.x += hv[e].x * exh;
                acc.y += hv[e].y * exh;
                acc.z += hv[e].z * exh;
                acc.w += hv[e].w * exh;
            }
        }
    }
    // lanes e*8+h hold den partials for head h: fold over e
    den_part += __shfl_xor_sync(0xffffffffu, den_part, 8);
    den_part += __shfl_xor_sync(0xffffffffu, den_part, 16);
    const float den = __shfl_sync(0xffffffffu, den_part, hq);
    const float inv = 1.f / (den + 1e-16f);
    acc.x *= inv; acc.y *= inv; acc.z *= inv; acc.w *= inv;
    *(float4*)&g_out1[d * HID + (lane << 2)] = acc;
}

// ---------------- K4: h2 = elu(out1+b1) @ W2 (FFMA2) + attention dots --------
// 64 threads (= out channel), 8 nodes per block.
__global__ void k4_gemm2(const float* __restrict__ W2, const float* __restrict__ b1,
                         const float* __restrict__ as2, const float* __restrict__ ad2) {
    __shared__ __align__(16) float hst[HID][8];      // [k][node]
    __shared__ float rbs[2][8], rbd[2][8];
    const int t = threadIdx.x;
    const int n0 = blockIdx.x * 8;

    for (int i = t; i < 8 * HID; i += 64) {
        const int j = i >> 7, k = i & 127;
        float v = g_out1[n0 * HID + i] + b1[k];
        hst[k][j] = v > 0.f ? v : (__expf(v) - 1.f);
    }
    __syncthreads();

    unsigned long long acc2[4] = {0ull, 0ull, 0ull, 0ull};
#pragma unroll
    for (int k = 0; k < HID; k++) {
        const float w = W2[k * OUT_DIM + t];
        const unsigned long long w2 = pack2(w, w);
#pragma unroll
        for (int jj = 0; jj < 4; jj++) {
            const unsigned long long xv =
                *(const unsigned long long*)&hst[k][jj * 2];
            acc2[jj] = ffma2(xv, w2, acc2[jj]);
        }
    }

    float accf[8];
#pragma unroll
    for (int jj = 0; jj < 4; jj++) unpack2(acc2[jj], accf[jj * 2], accf[jj * 2 + 1]);

    const float vas = as2[t], vad = ad2[t];
    const int wid = t >> 5;
#pragma unroll
    for (int j = 0; j < 8; j++) {
        g_h2[(n0 + j) * OUT_DIM + t] = accf[j];
        float vs = accf[j] * vas, vd = accf[j] * vad;
#pragma unroll
        for (int o = 16; o; o >>= 1) {
            vs += __shfl_xor_sync(0xffffffffu, vs, o);
            vd += __shfl_xor_sync(0xffffffffu, vd, o);
        }
        if ((t & 31) == 0) { rbs[wid][j] = vs; rbd[wid][j] = vd; }
    }
    __syncthreads();
    if (t < 8) {
        g_a2s[n0 + t] = rbs[0][t] + rbs[1][t];
        g_a2d[n0 + t] = rbd[0][t] + rbd[1][t];
    }
}

// ---------------- K6: CSR layer2 aggregation + bias + log_softmax -------------
// warp per dst node; lane owns 2 channels; one exp per lane per 32-edge chunk;
// 8-edge batched gathers for MLP.
__global__ void k6_lsm(const float* __restrict__ b2, float* __restrict__ out) {
    const int d = (blockIdx.x * blockDim.x + threadIdx.x) >> 5;
    const int lane = threadIdx.x & 31;
    if (d >= NN) return;

    const float a2d_d = __ldg(&g_a2d[d]);
    const int p0 = g_ptr[d], p1 = g_ptr[d + 1];
    float2 acc = make_float2(0.f, 0.f);
    float den = 0.f;

    for (int base = p0; base < p1; base += 32) {
        const int cnt = min(32, p1 - base);
        int s_r = 0;
        float e_r = 0.f;
        if (lane < cnt) {
            s_r = __ldg(&g_srcs[base + lane]);
            e_r = __expf(leaky(__ldg(&g_a2s[s_r]) + a2d_d));
            den += e_r;
        }
        for (int j0 = 0; j0 < cnt; j0 += 8) {
            float2 hv[8];
            float exv[8];
#pragma unroll
            for (int e = 0; e < 8; e++) {
                const int jj = (j0 + e) & 31;
                const int s = __shfl_sync(0xffffffffu, s_r, jj);
                exv[e] = __shfl_sync(0xffffffffu, e_r, jj);
                hv[e] = *(const float2*)&g_h2[s * OUT_DIM + lane * 2];
            }
#pragma unroll
            for (int e = 0; e < 8; e++) {
                acc.x += hv[e].x * exv[e];
                acc.y += hv[e].y * exv[e];
            }
        }
    }
#pragma unroll
    for (int o = 16; o; o >>= 1) den += __shfl_xor_sync(0xffffffffu, den, o);
    const float inv = 1.f / (den + 1e-16f);

    float vx = acc.x * inv + b2[lane * 2];
    float vy = acc.y * inv + b2[lane * 2 + 1];
    float m = fmaxf(vx, vy);
#pragma unroll
    for (int o = 16; o; o >>= 1) m = fmaxf(m, __shfl_xor_sync(0xffffffffu, m, o));
    float ssum = expf(vx - m) + expf(vy - m);
#pragma unroll
    for (int o = 16; o; o >>= 1) ssum += __shfl_xor_sync(0xffffffffu, ssum, o);
    const float lse = m + logf(ssum);
    *(float2*)&out[d * OUT_DIM + lane * 2] = make_float2(vx - lse, vy - lse);
}

// ---------------- launch ----------------
extern "C" void kernel_launch(void* const* d_in, const int* in_sizes, int n_in,
                              void* d_out, int out_size) {
    const float* x   = (const float*)d_in[0];
    const void*  ei  = d_in[1];
    const float* W1  = (const float*)d_in[2];
    const float* as1 = (const float*)d_in[3];
    const float* ad1 = (const float*)d_in[4];
    const float* b1  = (const float*)d_in[5];
    const float* W2  = (const float*)d_in[6];
    const float* as2 = (const float*)d_in[7];
    const float* ad2 = (const float*)d_in[8];
    const float* b2  = (const float*)d_in[9];
    float* out = (float*)d_out;

    // lazily-created side stream + events (host objects only; no device alloc)
    static cudaStream_t s1 = nullptr;
    static cudaEvent_t ev_fork = nullptr, ev_join = nullptr;
    if (s1 == nullptr) {
        cudaStreamCreateWithFlags(&s1, cudaStreamNonBlocking);
        cudaEventCreateWithFlags(&ev_fork, cudaEventDisableTiming);
        cudaEventCreateWithFlags(&ev_join, cudaEventDisableTiming);
    }

    void* pdeg;
    cudaGetSymbolAddress(&pdeg, g_deg);

    // fork: k1 (GEMM) runs on s1 concurrently with the CSR build on stream 0
    cudaEventRecord(ev_fork, 0);
    cudaStreamWaitEvent(s1, ev_fork, 0);
    k1_gemm1<<<(NN + 7) / 8, 128, 0, s1>>>(x, W1, as1, ad1);
    cudaEventRecord(ev_join, s1);

    // CSR build chain on stream 0
    cudaMemsetAsync(pdeg, 0, sizeof(int) * NN, 0);
    k0_detect<<<1, 256>>>((const long long*)ei);
    k0_hist<<<(ET + 255) / 256, 256>>>(ei);
    k0_scan<<<1, SCAN_T>>>();
    k0_scatter<<<(ET + 255) / 256, 256>>>(ei);

    // join: aggregation needs both CSR and h1
    cudaStreamWaitEvent(0, ev_join, 0);
    k3_agg1<<<(NN + 7) / 8, 256>>>();
    k4_gemm2<<<(NN + 7) / 8, 64>>>(W2, b1, as2, ad2);
    k6_lsm<<<(NN + 7) / 8, 256>>>(b2, out);
}

// round 13
// speedup vs baseline: 1.4262x; 1.3475x over previous
#include <cuda_runtime.h>
#include <cuda_fp16.h>
#include <math.h>

#define NN 50000
#define EE 800000
#define ET 850000   // EE + NN self loops
#define IN_DIM 128
#define HID 128
#define HEADS 8
#define OUT_DIM 64
#define NEG_SLOPE 0.2f
#define NB 49       // ceil(NN / 1024) scan blocks

// ---------------- scratch (device globals; no allocation) ----------------
__device__ __align__(16) float g_h1[NN * HID];
__device__ __align__(16) float g_a1s[NN * HEADS];
__device__ __align__(16) float g_a1d[NN * HEADS];
__device__ __align__(16) float g_out1[NN * HID];     // normalized layer1 agg
__device__ __align__(16) float g_h2[NN * OUT_DIM];
__device__ __align__(16) float g_a2s[NN];
__device__ __align__(16) float g_a2d[NN];
__device__ int g_deg[NN];
__device__ int g_ptr[NN + 1];
__device__ int g_pos[NN];
__device__ int g_bsum[64];
__device__ int g_boff[64];
__device__ int g_srcs[ET];                           // src sorted by dst
__device__ int g_is64;

__device__ __forceinline__ float leaky(float e) {
    return e > 0.f ? e : NEG_SLOPE * e;
}
// packed f32x2 FMA (FFMA2) — ptxas won't emit this on its own
__device__ __forceinline__ unsigned long long ffma2(unsigned long long a,
                                                    unsigned long long b,
                                                    unsigned long long c) {
    unsigned long long d;
    asm("fma.rn.f32x2 %0, %1, %2, %3;" : "=l"(d) : "l"(a), "l"(b), "l"(c));
    return d;
}
__device__ __forceinline__ unsigned long long pack2(float lo, float hi) {
    unsigned long long r;
    asm("mov.b64 %0, {%1, %2};" : "=l"(r) : "f"(lo), "f"(hi));
    return r;
}
__device__ __forceinline__ void unpack2(unsigned long long v, float& lo, float& hi) {
    asm("mov.b64 {%0, %1}, %2;" : "=f"(lo), "=f"(hi) : "l"(v));
}

// ---------------- K0a: detect edge_index dtype (int64 vs int32) ---------------
__global__ void k0_detect(const long long* __restrict__ ei) {
    __shared__ int bad;
    if (threadIdx.x == 0) bad = 0;
    __syncthreads();
    for (int i = threadIdx.x; i < 256; i += blockDim.x) {
        long long v = ei[i];
        if (v < 0 || v >= (long long)NN) bad = 1;
    }
    __syncthreads();
    if (threadIdx.x == 0) g_is64 = bad ? 0 : 1;
}

// ---------------- K0b: degree histogram (reads dst half directly) -------------
__global__ void k0_hist(const void* __restrict__ eiv) {
    const int i = blockIdx.x * blockDim.x + threadIdx.x;
    if (i >= ET) return;
    int d;
    if (i >= EE) d = i - EE;
    else if (g_is64) d = (int)((const long long*)eiv)[EE + i];
    else d = ((const int*)eiv)[EE + i];
    atomicAdd(&g_deg[d], 1);
}

// ---------------- K0c-A: block-local exclusive scan (49 blocks x 1024) --------
__global__ void k0_scanA() {
    __shared__ int wsum[32];
    const int gid = blockIdx.x * 1024 + threadIdx.x;
    const int lane = threadIdx.x & 31, wid = threadIdx.x >> 5;
    const int v = (gid < NN) ? g_deg[gid] : 0;
    int x = v;
#pragma unroll
    for (int o = 1; o < 32; o <<= 1) {
        const int y = __shfl_up_sync(0xffffffffu, x, o);
        if (lane >= o) x += y;
    }
    if (lane == 31) wsum[wid] = x;
    __syncthreads();
    if (wid == 0) {
        int s = wsum[lane];
#pragma unroll
        for (int o = 1; o < 32; o <<= 1) {
            const int y = __shfl_up_sync(0xffffffffu, s, o);
            if (lane >= o) s += y;
        }
        wsum[lane] = s;
    }
    __syncthreads();
    const int woff = wid ? wsum[wid - 1] : 0;
    if (gid < NN) g_ptr[gid] = woff + x - v;   // block-local exclusive
    if (threadIdx.x == 0) g_bsum[blockIdx.x] = wsum[31];
}

// ---------------- K0c-B: scan the 49 block sums (1 warp) ----------------------
__global__ void k0_scanB() {
    const int lane = threadIdx.x;
    const int i0 = lane * 2, i1 = lane * 2 + 1;
    const int v0 = (i0 < NB) ? g_bsum[i0] : 0;
    const int v1 = (i1 < NB) ? g_bsum[i1] : 0;
    const int p = v0 + v1;
    int x = p;
#pragma unroll
    for (int o = 1; o < 32; o <<= 1) {
        const int y = __shfl_up_sync(0xffffffffu, x, o);
        if (lane >= o) x += y;
    }
    const int excl = x - p;
    if (i0 < NB) g_boff[i0] = excl;
    if (i1 < NB) g_boff[i1] = excl + v0;
    if (lane == 31) g_ptr[NN] = x;   // grand total == ET
}

// ---------------- K0c-C: add block offsets, materialize ptr/pos ---------------
__global__ void k0_scanC() {
    const int gid = blockIdx.x * 1024 + threadIdx.x;
    if (gid < NN) {
        const int val = g_ptr[gid] + g_boff[blockIdx.x];
        g_ptr[gid] = val;
        g_pos[gid] = val;
    }
}

// ---------------- K0d: scatter srcs into dst-sorted order ---------------------
__global__ void k0_scatter(const void* __restrict__ eiv) {
    const int i = blockIdx.x * blockDim.x + threadIdx.x;
    if (i >= ET) return;
    int s, d;
    if (i >= EE) {
        s = d = i - EE;
    } else if (g_is64) {
        const long long* e = (const long long*)eiv;
        s = (int)e[i]; d = (int)e[EE + i];
    } else {
        const int* e = (const int*)eiv;
        s = e[i]; d = e[EE + i];
    }
    const int p = atomicAdd(&g_pos[d], 1);
    g_srcs[p] = s;
}

// ---------------- K1: h1 = x @ W1 (FFMA2) + per-head attention dots ----------
// 128 threads (= out channel), 8 nodes per block; xst transposed for f32x2.
__global__ void k1_gemm1(const float* __restrict__ x, const float* __restrict__ W1,
                         const float* __restrict__ as1, const float* __restrict__ ad1) {
    __shared__ __align__(16) float xst[IN_DIM][8];   // [k][node]
    const int t = threadIdx.x;
    const int n0 = blockIdx.x * 8;

    for (int i = t; i < 8 * IN_DIM; i += 128) {
        const int j = i >> 7, k = i & 127;
        xst[k][j] = x[n0 * IN_DIM + i];
    }
    __syncthreads();

    unsigned long long acc2[4] = {0ull, 0ull, 0ull, 0ull};
#pragma unroll
    for (int k = 0; k < IN_DIM; k++) {
        const float w = W1[k * HID + t];
        const unsigned long long w2 = pack2(w, w);
#pragma unroll
        for (int jj = 0; jj < 4; jj++) {
            const unsigned long long xv =
                *(const unsigned long long*)&xst[k][jj * 2];
            acc2[jj] = ffma2(xv, w2, acc2[jj]);
        }
    }

    float accf[8];
#pragma unroll
    for (int jj = 0; jj < 4; jj++) unpack2(acc2[jj], accf[jj * 2], accf[jj * 2 + 1]);

    const float vas = as1[t], vad = ad1[t];
#pragma unroll
    for (int j = 0; j < 8; j++) {
        g_h1[(n0 + j) * HID + t] = accf[j];
        float vs = accf[j] * vas, vd = accf[j] * vad;
#pragma unroll
        for (int o = 8; o; o >>= 1) {
            vs += __shfl_xor_sync(0xffffffffu, vs, o);
            vd += __shfl_xor_sync(0xffffffffu, vd, o);
        }
        if ((t & 15) == 0) {
            g_a1s[(n0 + j) * HEADS + (t >> 4)] = vs;
            g_a1d[(n0 + j) * HEADS + (t >> 4)] = vd;
        }
    }
}

// ---------------- K3: CSR layer1 aggregation (warp per dst node) --------------
// 8-edge batches: explicit load arrays force MLP=8 on the h1 gathers.
__global__ void k3_agg1() {
    const int d = (blockIdx.x * blockDim.x + threadIdx.x) >> 5;
    const int lane = threadIdx.x & 31;
    if (d >= NN) return;

    const int hq = lane >> 2;     // accumulation head (4 lanes each)
    const int esel = lane >> 3;   // 0..3: edge-in-group for exp duty
    const int hsel = lane & 7;    // head for exp duty
    const float a1d_h = (lane < 8) ? __ldg(&g_a1d[d * HEADS + lane]) : 0.f;
    const float a1d_all = __shfl_sync(0xffffffffu, a1d_h, hsel);

    const int p0 = g_ptr[d], p1 = g_ptr[d + 1];
    float4 acc = make_float4(0.f, 0.f, 0.f, 0.f);
    float den_part = 0.f;

    for (int base = p0; base < p1; base += 32) {
        const int cnt = min(32, p1 - base);
        int s_r = 0;
        if (lane < cnt) s_r = __ldg(&g_srcs[base + lane]);
        for (int j0 = 0; j0 < cnt; j0 += 8) {
            const int ja = j0 + esel;
            const int jb = j0 + 4 + esel;
            const int sa = __shfl_sync(0xffffffffu, s_r, min(ja, cnt - 1));
            const int sb = __shfl_sync(0xffffffffu, s_r, min(jb, cnt - 1) & 31);
            const float ex0 = (ja < cnt)
                ? __expf(leaky(__ldg(&g_a1s[sa * HEADS + hsel]) + a1d_all)) : 0.f;
            const float ex1 = (jb < cnt)
                ? __expf(leaky(__ldg(&g_a1s[sb * HEADS + hsel]) + a1d_all)) : 0.f;
            den_part += ex0 + ex1;

            float4 hv[8];
#pragma unroll
            for (int e = 0; e < 8; e++) {
                const int s2 = __shfl_sync(0xffffffffu, s_r, min(j0 + e, cnt - 1));
                hv[e] = *(const float4*)&g_h1[s2 * HID + (lane << 2)];
            }
#pragma unroll
            for (int e = 0; e < 8; e++) {
                const float exs = (e < 4) ? ex0 : ex1;
                const float exh = __shfl_sync(0xffffffffu, exs, ((e & 3) << 3) | hq);
                acc.x += hv[e].x * exh;
                acc.y += hv[e].y * exh;
                acc.z += hv[e].z * exh;
                acc.w += hv[e].w * exh;
            }
        }
    }
    // lanes e*8+h hold den partials for head h: fold over e
    den_part += __shfl_xor_sync(0xffffffffu, den_part, 8);
    den_part += __shfl_xor_sync(0xffffffffu, den_part, 16);
    const float den = __shfl_sync(0xffffffffu, den_part, hq);
    const float inv = 1.f / (den + 1e-16f);
    acc.x *= inv; acc.y *= inv; acc.z *= inv; acc.w *= inv;
    *(float4*)&g_out1[d * HID + (lane << 2)] = acc;
}

// ---------------- K4: h2 = elu(out1+b1) @ W2 (FFMA2) + attention dots --------
// 64 threads (= out channel), 8 nodes per block.
__global__ void k4_gemm2(const float* __restrict__ W2, const float* __restrict__ b1,
                         const float* __restrict__ as2, const float* __restrict__ ad2) {
    __shared__ __align__(16) float hst[HID][8];      // [k][node]
    __shared__ float rbs[2][8], rbd[2][8];
    const int t = threadIdx.x;
    const int n0 = blockIdx.x * 8;

    for (int i = t; i < 8 * HID; i += 64) {
        const int j = i >> 7, k = i & 127;
        float v = g_out1[n0 * HID + i] + b1[k];
        hst[k][j] = v > 0.f ? v : (__expf(v) - 1.f);
    }
    __syncthreads();

    unsigned long long acc2[4] = {0ull, 0ull, 0ull, 0ull};
#pragma unroll
    for (int k = 0; k < HID; k++) {
        const float w = W2[k * OUT_DIM + t];
        const unsigned long long w2 = pack2(w, w);
#pragma unroll
        for (int jj = 0; jj < 4; jj++) {
            const unsigned long long xv =
                *(const unsigned long long*)&hst[k][jj * 2];
            acc2[jj] = ffma2(xv, w2, acc2[jj]);
        }
    }

    float accf[8];
#pragma unroll
    for (int jj = 0; jj < 4; jj++) unpack2(acc2[jj], accf[jj * 2], accf[jj * 2 + 1]);

    const float vas = as2[t], vad = ad2[t];
    const int wid = t >> 5;
#pragma unroll
    for (int j = 0; j < 8; j++) {
        g_h2[(n0 + j) * OUT_DIM + t] = accf[j];
        float vs = accf[j] * vas, vd = accf[j] * vad;
#pragma unroll
        for (int o = 16; o; o >>= 1) {
            vs += __shfl_xor_sync(0xffffffffu, vs, o);
            vd += __shfl_xor_sync(0xffffffffu, vd, o);
        }
        if ((t & 31) == 0) { rbs[wid][j] = vs; rbd[wid][j] = vd; }
    }
    __syncthreads();
    if (t < 8) {
        g_a2s[n0 + t] = rbs[0][t] + rbs[1][t];
        g_a2d[n0 + t] = rbd[0][t] + rbd[1][t];
    }
}

// ---------------- K6: CSR layer2 aggregation + bias + log_softmax -------------
__global__ void k6_lsm(const float* __restrict__ b2, float* __restrict__ out) {
    const int d = (blockIdx.x * blockDim.x + threadIdx.x) >> 5;
    const int lane = threadIdx.x & 31;
    if (d >= NN) return;

    const float a2d_d = __ldg(&g_a2d[d]);
    const int p0 = g_ptr[d], p1 = g_ptr[d + 1];
    float2 acc = make_float2(0.f, 0.f);
    float den = 0.f;

    for (int base = p0; base < p1; base += 32) {
        const int cnt = min(32, p1 - base);
        int s_r = 0;
        float e_r = 0.f;
        if (lane < cnt) {
            s_r = __ldg(&g_srcs[base + lane]);
            e_r = __expf(leaky(__ldg(&g_a2s[s_r]) + a2d_d));
            den += e_r;
        }
        for (int j0 = 0; j0 < cnt; j0 += 8) {
            float2 hv[8];
            float exv[8];
#pragma unroll
            for (int e = 0; e < 8; e++) {
                const int jj = (j0 + e) & 31;
                const int s = __shfl_sync(0xffffffffu, s_r, jj);
                exv[e] = __shfl_sync(0xffffffffu, e_r, jj);
                hv[e] = *(const float2*)&g_h2[s * OUT_DIM + lane * 2];
            }
#pragma unroll
            for (int e = 0; e < 8; e++) {
                acc.x += hv[e].x * exv[e];
                acc.y += hv[e].y * exv[e];
            }
        }
    }
#pragma unroll
    for (int o = 16; o; o >>= 1) den += __shfl_xor_sync(0xffffffffu, den, o);
    const float inv = 1.f / (den + 1e-16f);

    float vx = acc.x * inv + b2[lane * 2];
    float vy = acc.y * inv + b2[lane * 2 + 1];
    float m = fmaxf(vx, vy);
#pragma unroll
    for (int o = 16; o; o >>= 1) m = fmaxf(m, __shfl_xor_sync(0xffffffffu, m, o));
    float ssum = expf(vx - m) + expf(vy - m);
#pragma unroll
    for (int o = 16; o; o >>= 1) ssum += __shfl_xor_sync(0xffffffffu, ssum, o);
    const float lse = m + logf(ssum);
    *(float2*)&out[d * OUT_DIM + lane * 2] = make_float2(vx - lse, vy - lse);
}

// ---------------- launch ----------------
extern "C" void kernel_launch(void* const* d_in, const int* in_sizes, int n_in,
                              void* d_out, int out_size) {
    const float* x   = (const float*)d_in[0];
    const void*  ei  = d_in[1];
    const float* W1  = (const float*)d_in[2];
    const float* as1 = (const float*)d_in[3];
    const float* ad1 = (const float*)d_in[4];
    const float* b1  = (const float*)d_in[5];
    const float* W2  = (const float*)d_in[6];
    const float* as2 = (const float*)d_in[7];
    const float* ad2 = (const float*)d_in[8];
    const float* b2  = (const float*)d_in[9];
    float* out = (float*)d_out;

    // lazily-created side stream + events (host objects only; no device alloc)
    static cudaStream_t s1 = nullptr;
    static cudaEvent_t ev_fork = nullptr, ev_join = nullptr;
    if (s1 == nullptr) {
        cudaStreamCreateWithFlags(&s1, cudaStreamNonBlocking);
        cudaEventCreateWithFlags(&ev_fork, cudaEventDisableTiming);
        cudaEventCreateWithFlags(&ev_join, cudaEventDisableTiming);
    }

    void* pdeg;
    cudaGetSymbolAddress(&pdeg, g_deg);

    // fork: k1 (GEMM) runs on s1 concurrently with the CSR build on stream 0
    cudaEventRecord(ev_fork, 0);
    cudaStreamWaitEvent(s1, ev_fork, 0);
    k1_gemm1<<<(NN + 7) / 8, 128, 0, s1>>>(x, W1, as1, ad1);
    cudaEventRecord(ev_join, s1);

    // CSR build chain on stream 0
    cudaMemsetAsync(pdeg, 0, sizeof(int) * NN, 0);
    k0_detect<<<1, 256>>>((const long long*)ei);
    k0_hist<<<(ET + 255) / 256, 256>>>(ei);
    k0_scanA<<<NB, 1024>>>();
    k0_scanB<<<1, 32>>>();
    k0_scanC<<<NB, 1024>>>();
    k0_scatter<<<(ET + 255) / 256, 256>>>(ei);

    // join: aggregation needs both CSR and h1
    cudaStreamWaitEvent(0, ev_join, 0);
    k3_agg1<<<(NN + 7) / 8, 256>>>();
    k4_gemm2<<<(NN + 7) / 8, 64>>>(W2, b1, as2, ad2);
    k6_lsm<<<(NN + 7) / 8, 256>>>(b2, out);
}

// round 15
// speedup vs baseline: 1.4432x; 1.0119x over previous
#include <cuda_runtime.h>
#include <cuda_fp16.h>
#include <math.h>

#define NN 50000
#define EE 800000
#define ET 850000   // EE + NN self loops
#define IN_DIM 128
#define HID 128
#define HEADS 8
#define OUT_DIM 64
#define NEG_SLOPE 0.2f
#define NB 49       // ceil(NN / 1024) scan blocks

// ---------------- scratch (device globals; no allocation) ----------------
__device__ __align__(16) __half g_h1[NN * HID];      // fp16 layer1 features
__device__ __align__(16) float g_a1s[NN * HEADS];
__device__ __align__(16) float g_a1d[NN * HEADS];
__device__ __align__(16) float g_out1[NN * HID];     // normalized layer1 agg (fp32)
__device__ __align__(16) __half g_h2[NN * OUT_DIM];  // fp16 layer2 features
__device__ __align__(16) float g_a2s[NN];
__device__ __align__(16) float g_a2d[NN];
__device__ int g_deg[NN];
__device__ int g_ptr[NN + 1];
__device__ int g_pos[NN];
__device__ int g_bsum[64];
__device__ int g_boff[64];
__device__ int g_srcs[ET];                           // src sorted by dst
__device__ int g_is64;

__device__ __forceinline__ float leaky(float e) {
    return e > 0.f ? e : NEG_SLOPE * e;
}
// packed f32x2 FMA (FFMA2) — ptxas won't emit this on its own
__device__ __forceinline__ unsigned long long ffma2(unsigned long long a,
                                                    unsigned long long b,
                                                    unsigned long long c) {
    unsigned long long d;
    asm("fma.rn.f32x2 %0, %1, %2, %3;" : "=l"(d) : "l"(a), "l"(b), "l"(c));
    return d;
}
__device__ __forceinline__ unsigned long long pack2(float lo, float hi) {
    unsigned long long r;
    asm("mov.b64 %0, {%1, %2};" : "=l"(r) : "f"(lo), "f"(hi));
    return r;
}
__device__ __forceinline__ void unpack2(unsigned long long v, float& lo, float& hi) {
    asm("mov.b64 {%0, %1}, %2;" : "=f"(lo), "=f"(hi) : "l"(v));
}

// ---------------- K0a: detect edge_index dtype (int64 vs int32) ---------------
__global__ void k0_detect(const long long* __restrict__ ei) {
    __shared__ int bad;
    if (threadIdx.x == 0) bad = 0;
    __syncthreads();
    for (int i = threadIdx.x; i < 256; i += blockDim.x) {
        long long v = ei[i];
        if (v < 0 || v >= (long long)NN) bad = 1;
    }
    __syncthreads();
    if (threadIdx.x == 0) g_is64 = bad ? 0 : 1;
}

// ---------------- K0b: degree histogram (reads dst half directly) -------------
__global__ void k0_hist(const void* __restrict__ eiv) {
    const int i = blockIdx.x * blockDim.x + threadIdx.x;
    if (i >= ET) return;
    int d;
    if (i >= EE) d = i - EE;
    else if (g_is64) d = (int)((const long long*)eiv)[EE + i];
    else d = ((const int*)eiv)[EE + i];
    atomicAdd(&g_deg[d], 1);
}

// ---------------- K0c-A: block-local exclusive scan (49 blocks x 1024) --------
__global__ void k0_scanA() {
    __shared__ int wsum[32];
    const int gid = blockIdx.x * 1024 + threadIdx.x;
    const int lane = threadIdx.x & 31, wid = threadIdx.x >> 5;
    const int v = (gid < NN) ? g_deg[gid] : 0;
    int x = v;
#pragma unroll
    for (int o = 1; o < 32; o <<= 1) {
        const int y = __shfl_up_sync(0xffffffffu, x, o);
        if (lane >= o) x += y;
    }
    if (lane == 31) wsum[wid] = x;
    __syncthreads();
    if (wid == 0) {
        int s = wsum[lane];
#pragma unroll
        for (int o = 1; o < 32; o <<= 1) {
            const int y = __shfl_up_sync(0xffffffffu, s, o);
            if (lane >= o) s += y;
        }
        wsum[lane] = s;
    }
    __syncthreads();
    const int woff = wid ? wsum[wid - 1] : 0;
    if (gid < NN) g_ptr[gid] = woff + x - v;   // block-local exclusive
    if (threadIdx.x == 0) g_bsum[blockIdx.x] = wsum[31];
}

// ---------------- K0c-B: scan the 49 block sums (1 warp) ----------------------
__global__ void k0_scanB() {
    const int lane = threadIdx.x;
    const int i0 = lane * 2, i1 = lane * 2 + 1;
    const int v0 = (i0 < NB) ? g_bsum[i0] : 0;
    const int v1 = (i1 < NB) ? g_bsum[i1] : 0;
    const int p = v0 + v1;
    int x = p;
#pragma unroll
    for (int o = 1; o < 32; o <<= 1) {
        const int y = __shfl_up_sync(0xffffffffu, x, o);
        if (lane >= o) x += y;
    }
    const int excl = x - p;
    if (i0 < NB) g_boff[i0] = excl;
    if (i1 < NB) g_boff[i1] = excl + v0;
    if (lane == 31) g_ptr[NN] = x;   // grand total == ET
}

// ---------------- K0c-C: add block offsets, materialize ptr/pos ---------------
__global__ void k0_scanC() {
    const int gid = blockIdx.x * 1024 + threadIdx.x;
    if (gid < NN) {
        const int val = g_ptr[gid] + g_boff[blockIdx.x];
        g_ptr[gid] = val;
        g_pos[gid] = val;
    }
}

// ---------------- K0d: scatter srcs into dst-sorted order ---------------------
__global__ void k0_scatter(const void* __restrict__ eiv) {
    const int i = blockIdx.x * blockDim.x + threadIdx.x;
    if (i >= ET) return;
    int s, d;
    if (i >= EE) {
        s = d = i - EE;
    } else if (g_is64) {
        const long long* e = (const long long*)eiv;
        s = (int)e[i]; d = (int)e[EE + i];
    } else {
        const int* e = (const int*)eiv;
        s = e[i]; d = e[EE + i];
    }
    const int p = atomicAdd(&g_pos[d], 1);
    g_srcs[p] = s;
}

// ---------------- K1: h1 = x @ W1 (FFMA2) + per-head attention dots ----------
// 128 threads (= out channel), 8 nodes per block; xst transposed for f32x2.
__global__ void k1_gemm1(const float* __restrict__ x, const float* __restrict__ W1,
                         const float* __restrict__ as1, const float* __restrict__ ad1) {
    __shared__ __align__(16) float xst[IN_DIM][8];   // [k][node]
    const int t = threadIdx.x;
    const int n0 = blockIdx.x * 8;

    for (int i = t; i < 8 * IN_DIM; i += 128) {
        const int j = i >> 7, k = i & 127;
        xst[k][j] = x[n0 * IN_DIM + i];
    }
    __syncthreads();

    unsigned long long acc2[4] = {0ull, 0ull, 0ull, 0ull};
#pragma unroll
    for (int k = 0; k < IN_DIM; k++) {
        const float w = W1[k * HID + t];
        const unsigned long long w2 = pack2(w, w);
#pragma unroll
        for (int jj = 0; jj < 4; jj++) {
            const unsigned long long xv =
                *(const unsigned long long*)&xst[k][jj * 2];
            acc2[jj] = ffma2(xv, w2, acc2[jj]);
        }
    }

    float accf[8];
#pragma unroll
    for (int jj = 0; jj < 4; jj++) unpack2(acc2[jj], accf[jj * 2], accf[jj * 2 + 1]);

    const float vas = as1[t], vad = ad1[t];
#pragma unroll
    for (int j = 0; j < 8; j++) {
        g_h1[(n0 + j) * HID + t] = __float2half(accf[j]);
        float vs = accf[j] * vas, vd = accf[j] * vad;
#pragma unroll
        for (int o = 8; o; o >>= 1) {
            vs += __shfl_xor_sync(0xffffffffu, vs, o);
            vd += __shfl_xor_sync(0xffffffffu, vd, o);
        }
        if ((t & 15) == 0) {
            g_a1s[(n0 + j) * HEADS + (t >> 4)] = vs;
            g_a1d[(n0 + j) * HEADS + (t >> 4)] = vd;
        }
    }
}

// ---------------- K3: CSR layer1 aggregation (warp per dst node) --------------
// 8-edge batches: explicit load arrays force MLP=8 on the fp16 h1 gathers.
__global__ void k3_agg1() {
    const int d = (blockIdx.x * blockDim.x + threadIdx.x) >> 5;
    const int lane = threadIdx.x & 31;
    if (d >= NN) return;

    const int hq = lane >> 2;     // accumulation head (4 lanes each)
    const int esel = lane >> 3;   // 0..3: edge-in-group for exp duty
    const int hsel = lane & 7;    // head for exp duty
    const float a1d_h = (lane < 8) ? __ldg(&g_a1d[d * HEADS + lane]) : 0.f;
    const float a1d_all = __shfl_sync(0xffffffffu, a1d_h, hsel);

    const int p0 = g_ptr[d], p1 = g_ptr[d + 1];
    float4 acc = make_float4(0.f, 0.f, 0.f, 0.f);
    float den_part = 0.f;

    for (int base = p0; base < p1; base += 32) {
        const int cnt = min(32, p1 - base);
        int s_r = 0;
        if (lane < cnt) s_r = __ldg(&g_srcs[base + lane]);
        for (int j0 = 0; j0 < cnt; j0 += 8) {
            const int ja = j0 + esel;
            const int jb = j0 + 4 + esel;
            const int sa = __shfl_sync(0xffffffffu, s_r, min(ja, cnt - 1));
            const int sb = __shfl_sync(0xffffffffu, s_r, min(jb, cnt - 1) & 31);
            const float ex0 = (ja < cnt)
                ? __expf(leaky(__ldg(&g_a1s[sa * HEADS + hsel]) + a1d_all)) : 0.f;
            const float ex1 = (jb < cnt)
                ? __expf(leaky(__ldg(&g_a1s[sb * HEADS + hsel]) + a1d_all)) : 0.f;
            den_part += ex0 + ex1;

            uint2 hv[8];   // 4 halves per lane per edge
#pragma unroll
            for (int e = 0; e < 8; e++) {
                const int s2 = __shfl_sync(0xffffffffu, s_r, min(j0 + e, cnt - 1));
                hv[e] = *(const uint2*)&g_h1[s2 * HID + (lane << 2)];
            }
#pragma unroll
            for (int e = 0; e < 8; e++) {
                const float exs = (e < 4) ? ex0 : ex1;
                const float exh = __shfl_sync(0xffffffffu, exs, ((e & 3) << 3) | hq);
                const float2 f0 = __half22float2(*(const __half2*)&hv[e].x);
                const float2 f1 = __half22float2(*(const __half2*)&hv[e].y);
                acc.x += f0.x * exh;
                acc.y += f0.y * exh;
                acc.z += f1.x * exh;
                acc.w += f1.y * exh;
            }
        }
    }
    // lanes e*8+h hold den partials for head h: fold over e
    den_part += __shfl_xor_sync(0xffffffffu, den_part, 8);
    den_part += __shfl_xor_sync(0xffffffffu, den_part, 16);
    const float den = __shfl_sync(0xffffffffu, den_part, hq);
    const float inv = 1.f / (den + 1e-16f);
    acc.x *= inv; acc.y *= inv; acc.z *= inv; acc.w *= inv;
    *(float4*)&g_out1[d * HID + (lane << 2)] = acc;
}

// ---------------- K4: h2 = elu(out1+b1) @ W2 (FFMA2) + attention dots --------
// 64 threads (= out channel), 8 nodes per block.
__global__ void k4_gemm2(const float* __restrict__ W2, const float* __restrict__ b1,
                         const float* __restrict__ as2, const float* __restrict__ ad2) {
    __shared__ __align__(16) float hst[HID][8];      // [k][node]
    __shared__ float rbs[2][8], rbd[2][8];
    const int t = threadIdx.x;
    const int n0 = blockIdx.x * 8;

    for (int i = t; i < 8 * HID; i += 64) {
        const int j = i >> 7, k = i & 127;
        float v = g_out1[n0 * HID + i] + b1[k];
        hst[k][j] = v > 0.f ? v : (__expf(v) - 1.f);
    }
    __syncthreads();

    unsigned long long acc2[4] = {0ull, 0ull, 0ull, 0ull};
#pragma unroll
    for (int k = 0; k < HID; k++) {
        const float w = W2[k * OUT_DIM + t];
        const unsigned long long w2 = pack2(w, w);
#pragma unroll
        for (int jj = 0; jj < 4; jj++) {
            const unsigned long long xv =
                *(const unsigned long long*)&hst[k][jj * 2];
            acc2[jj] = ffma2(xv, w2, acc2[jj]);
        }
    }

    float accf[8];
#pragma unroll
    for (int jj = 0; jj < 4; jj++) unpack2(acc2[jj], accf[jj * 2], accf[jj * 2 + 1]);

    const float vas = as2[t], vad = ad2[t];
    const int wid = t >> 5;
#pragma unroll
    for (int j = 0; j < 8; j++) {
        g_h2[(n0 + j) * OUT_DIM + t] = __float2half(accf[j]);
        float vs = accf[j] * vas, vd = accf[j] * vad;
#pragma unroll
        for (int o = 16; o; o >>= 1) {
            vs += __shfl_xor_sync(0xffffffffu, vs, o);
            vd += __shfl_xor_sync(0xffffffffu, vd, o);
        }
        if ((t & 31) == 0) { rbs[wid][j] = vs; rbd[wid][j] = vd; }
    }
    __syncthreads();
    if (t < 8) {
        g_a2s[n0 + t] = rbs[0][t] + rbs[1][t];
        g_a2d[n0 + t] = rbd[0][t] + rbd[1][t];
    }
}

// ---------------- K6: CSR layer2 aggregation + bias + log_softmax -------------
__global__ void k6_lsm(const float* __restrict__ b2, float* __restrict__ out) {
    const int d = (blockIdx.x * blockDim.x + threadIdx.x) >> 5;
    const int lane = threadIdx.x & 31;
    if (d >= NN) return;

    const float a2d_d = __ldg(&g_a2d[d]);
    const int p0 = g_ptr[d], p1 = g_ptr[d + 1];
    float2 acc = make_float2(0.f, 0.f);
    float den = 0.f;

    for (int base = p0; base < p1; base += 32) {
        const int cnt = min(32, p1 - base);
        int s_r = 0;
        float e_r = 0.f;
        if (lane < cnt) {
            s_r = __ldg(&g_srcs[base + lane]);
            e_r = __expf(leaky(__ldg(&g_a2s[s_r]) + a2d_d));
            den += e_r;
        }
        for (int j0 = 0; j0 < cnt; j0 += 8) {
            __half2 hv[8];
            float exv[8];
#pragma unroll
            for (int e = 0; e < 8; e++) {
                const int jj = (j0 + e) & 31;
                const int s = __shfl_sync(0xffffffffu, s_r, jj);
                exv[e] = __shfl_sync(0xffffffffu, e_r, jj);
                hv[e] = *(const __half2*)&g_h2[s * OUT_DIM + lane * 2];
            }
#pragma unroll
            for (int e = 0; e < 8; e++) {
                const float2 f = __half22float2(hv[e]);
                acc.x += f.x * exv[e];
                acc.y += f.y * exv[e];
            }
        }
    }
#pragma unroll
    for (int o = 16; o; o >>= 1) den += __shfl_xor_sync(0xffffffffu, den, o);
    const float inv = 1.f / (den + 1e-16f);

    float vx = acc.x * inv + b2[lane * 2];
    float vy = acc.y * inv + b2[lane * 2 + 1];
    float m = fmaxf(vx, vy);
#pragma unroll
    for (int o = 16; o; o >>= 1) m = fmaxf(m, __shfl_xor_sync(0xffffffffu, m, o));
    float ssum = expf(vx - m) + expf(vy - m);
#pragma unroll
    for (int o = 16; o; o >>= 1) ssum += __shfl_xor_sync(0xffffffffu, ssum, o);
    const float lse = m + logf(ssum);
    *(float2*)&out[d * OUT_DIM + lane * 2] = make_float2(vx - lse, vy - lse);
}

// ---------------- launch ----------------
extern "C" void kernel_launch(void* const* d_in, const int* in_sizes, int n_in,
                              void* d_out, int out_size) {
    const float* x   = (const float*)d_in[0];
    const void*  ei  = d_in[1];
    const float* W1  = (const float*)d_in[2];
    const float* as1 = (const float*)d_in[3];
    const float* ad1 = (const float*)d_in[4];
    const float* b1  = (const float*)d_in[5];
    const float* W2  = (const float*)d_in[6];
    const float* as2 = (const float*)d_in[7];
    const float* ad2 = (const float*)d_in[8];
    const float* b2  = (const float*)d_in[9];
    float* out = (float*)d_out;

    // lazily-created side stream + events (host objects only; no device alloc)
    static cudaStream_t s1 = nullptr;
    static cudaEvent_t ev_fork = nullptr, ev_join = nullptr;
    if (s1 == nullptr) {
        cudaStreamCreateWithFlags(&s1, cudaStreamNonBlocking);
        cudaEventCreateWithFlags(&ev_fork, cudaEventDisableTiming);
        cudaEventCreateWithFlags(&ev_join, cudaEventDisableTiming);
    }

    void* pdeg;
    cudaGetSymbolAddress(&pdeg, g_deg);

    // fork: k1 (GEMM) runs on s1 concurrently with the CSR build on stream 0
    cudaEventRecord(ev_fork, 0);
    cudaStreamWaitEvent(s1, ev_fork, 0);
    k1_gemm1<<<(NN + 7) / 8, 128, 0, s1>>>(x, W1, as1, ad1);
    cudaEventRecord(ev_join, s1);

    // CSR build chain on stream 0
    cudaMemsetAsync(pdeg, 0, sizeof(int) * NN, 0);
    k0_detect<<<1, 256>>>((const long long*)ei);
    k0_hist<<<(ET + 255) / 256, 256>>>(ei);
    k0_scanA<<<NB, 1024>>>();
    k0_scanB<<<1, 32>>>();
    k0_scanC<<<NB, 1024>>>();
    k0_scatter<<<(ET + 255) / 256, 256>>>(ei);

    // join: aggregation needs both CSR and h1
    cudaStreamWaitEvent(0, ev_join, 0);
    k3_agg1<<<(NN + 7) / 8, 256>>>();
    k4_gemm2<<<(NN + 7) / 8, 64>>>(W2, b1, as2, ad2);
    k6_lsm<<<(NN + 7) / 8, 256>>>(b2, out);
}